// round 3
// baseline (speedup 1.0000x reference)
#include <cuda_runtime.h>

// VisibilityHeatmap: per (b,k) keypoint, NDC coord -> pixel index, gather ONE
// heatmap value, threshold, broadcast mask to both coord lanes.
//
// coords [B=32,K=64,2] f32, heatmaps [B,K,256,256] f32, out [B,K,2] f32.
// Latency-bound micro-kernel (2048 keypoints, ~260KB touched of 512MB).
// This round: 2 keypoints per thread -> half the warps, float4 I/O, two
// independent gathers per thread (MLP=2, one overlapped round trip).

#define THRESHOLD 0.4f

__global__ void __launch_bounds__(256, 1)
vis_heatmap_kernel(const float4* __restrict__ coords,   // [n/2] float4 = 2 keypoints
                   const float* __restrict__ heatmaps,
                   float4* __restrict__ out,             // [n/2] float4 = 2 masks
                   int npairs)
{
    int i = blockIdx.x * blockDim.x + threadIdx.x;
    if (i >= npairs) return;

    // One float4 = coords of keypoints (2i) and (2i+1)
    float4 c = coords[i];

    // ndc -> pixel, truncate toward zero (matches .astype(int32))
    int u0 = (int)((c.x + 1.0f) * 128.0f);
    int v0 = (int)((c.y + 1.0f) * 128.0f);
    int u1 = (int)((c.z + 1.0f) * 128.0f);
    int v1 = (int)((c.w + 1.0f) * 128.0f);

    bool valid0 = ((unsigned)u0 < 256u) & ((unsigned)v0 < 256u);
    bool valid1 = ((unsigned)u1 < 256u) & ((unsigned)v1 < 256u);

    // Two independent predicated gathers: heatmaps[k][v][u], k = 2i / 2i+1.
    // Address = (k << 16) | (v << 8) | u  (u,v in [0,256) when valid).
    float val0 = 0.0f, val1 = 0.0f;
    if (valid0) {
        unsigned idx0 = ((unsigned)(2 * i) << 16) | ((unsigned)v0 << 8) | (unsigned)u0;
        val0 = __ldg(&heatmaps[idx0]);
    }
    if (valid1) {
        unsigned idx1 = ((unsigned)(2 * i + 1) << 16) | ((unsigned)v1 << 8) | (unsigned)u1;
        val1 = __ldg(&heatmaps[idx1]);
    }

    float m0 = (val0 > THRESHOLD) ? 1.0f : 0.0f;
    float m1 = (val1 > THRESHOLD) ? 1.0f : 0.0f;

    out[i] = make_float4(m0, m0, m1, m1);
}

extern "C" void kernel_launch(void* const* d_in, const int* in_sizes, int n_in,
                              void* d_out, int out_size)
{
    const float4* coords   = (const float4*)d_in[0];
    const float*  heatmaps = (const float*)d_in[1];
    float4* out = (float4*)d_out;

    int n = in_sizes[0] / 2;   // B*K keypoints
    int npairs = n / 2;        // 2 keypoints per thread (B*K is even: 2048)

    int threads = 256;
    int blocks = (npairs + threads - 1) / threads;
    vis_heatmap_kernel<<<blocks, threads>>>(coords, heatmaps, out, npairs);
}

// round 4
// speedup vs baseline: 1.0093x; 1.0093x over previous
#include <cuda_runtime.h>

// VisibilityHeatmap: per (b,k) keypoint, NDC coord -> pixel index, gather ONE
// heatmap value, threshold, broadcast mask to both coord lanes.
//
// coords [B=32,K=64,2] f32, heatmaps [B,K,256,256] f32, out [B,K,2] f32.
// Latency-bound micro-kernel: 2048 independent gathers. Spread across as many
// SMs as possible: 64 CTAs x 32 threads = 1 warp/SM on 64 SMs, each warp
// exposes exactly one coord-load -> gather -> store chain. (R3's 2-kp/thread
// + grid=4 concentrated work on 4 SMs and regressed; reverted.)

#define THRESHOLD 0.4f

__global__ void __launch_bounds__(32, 1)
vis_heatmap_kernel(const float* __restrict__ coords,
                   const float* __restrict__ heatmaps,
                   float* __restrict__ out)
{
    // Exact-fit launch: 64 blocks x 32 threads = 2048 = B*K, no bounds guard.
    int i = blockIdx.x * 32 + threadIdx.x;

    // Coalesced vectorized coord load: (u, v) NDC
    float2 c = reinterpret_cast<const float2*>(coords)[i];

    // ndc -> pixel, truncate toward zero (matches .astype(int32))
    int u = (int)((c.x + 1.0f) * 128.0f);   // 0.5 * WIDTH  = 128
    int v = (int)((c.y + 1.0f) * 128.0f);   // 0.5 * HEIGHT = 128

    // valid iff 0 <= u < 256 and 0 <= v < 256
    bool valid = ((unsigned)u < 256u) & ((unsigned)v < 256u);

    // Predicated gather: invalid lanes output 0 regardless, so skip the load.
    float val = 0.0f;
    if (valid) {
        // heatmaps[i][v][u] = base + ((i<<16) | (v<<8) | u)
        unsigned idx = ((unsigned)i << 16) | ((unsigned)v << 8) | (unsigned)u;
        val = __ldg(&heatmaps[idx]);
    }

    float m = (val > THRESHOLD) ? 1.0f : 0.0f;

    // Coalesced vectorized store: broadcast mask to both lanes
    reinterpret_cast<float2*>(out)[i] = make_float2(m, m);
}

extern "C" void kernel_launch(void* const* d_in, const int* in_sizes, int n_in,
                              void* d_out, int out_size)
{
    const float* coords   = (const float*)d_in[0];
    const float* heatmaps = (const float*)d_in[1];
    float* out = (float*)d_out;

    int n = in_sizes[0] / 2;       // B*K keypoints = 2048
    int blocks = (n + 31) / 32;    // 64 CTAs x 32 threads, exact fit
    vis_heatmap_kernel<<<blocks, 32>>>(coords, heatmaps, out);
}